// round 17
// baseline (speedup 1.0000x reference)
#include <cuda_runtime.h>
#include <cuda_bf16.h>
#include <math.h>
#include <stdint.h>

#define DIMD   512
#define HEADS  8
#define HD     64
#define MLPD   2048
#define BATCH  2
#define SEQ    4096
#define BN_TOK 8192   // BATCH*SEQ
#define QKVD   1536   // 3*DIMD

// ---------------- scratch (static device arrays; no allocation) -------------
__device__ float g_qkv[(size_t)BN_TOK * QKVD];
__device__ float g_xm [(size_t)BN_TOK * DIMD];
__device__ __nv_bfloat16 g_h2h[(size_t)BN_TOK * DIMD];
__device__ __nv_bfloat16 g_h2l[(size_t)BN_TOK * DIMD];
__device__ __nv_bfloat16 g_atth[(size_t)BN_TOK * DIMD];
__device__ __nv_bfloat16 g_attl[(size_t)BN_TOK * DIMD];
__device__ __nv_bfloat16 g_ffh[(size_t)BN_TOK * MLPD];
__device__ __nv_bfloat16 g_ffl[(size_t)BN_TOK * MLPD];
// transposed + split weights [N][K]
__device__ __nv_bfloat16 g_wqkvh[(size_t)QKVD * DIMD], g_wqkvl[(size_t)QKVD * DIMD];
__device__ __nv_bfloat16 g_woh[(size_t)DIMD * DIMD],  g_wol[(size_t)DIMD * DIMD];
__device__ __nv_bfloat16 g_w1h[(size_t)MLPD * DIMD],  g_w1l[(size_t)MLPD * DIMD];
__device__ __nv_bfloat16 g_w2h[(size_t)DIMD * MLPD],  g_w2l[(size_t)DIMD * MLPD];

__device__ __forceinline__ float gelu_exact(float x) {
    return 0.5f * x * (1.0f + erff(x * 0.70710678118654752440f));
}
__device__ __forceinline__ uint32_t pack2_bf16(float a, float b) {
    __nv_bfloat162 t = __floats2bfloat162_rn(a, b);
    return *reinterpret_cast<uint32_t*>(&t);
}
__device__ __forceinline__ void split_bf16(float x, __nv_bfloat16& hi, __nv_bfloat16& lo) {
    hi = __float2bfloat16_rn(x);
    lo = __float2bfloat16_rn(x - __bfloat162float(hi));
}
__device__ __forceinline__ uint32_t smem_u32(const void* p) {
    uint32_t a;
    asm("{ .reg .u64 t; cvta.to.shared.u64 t, %1; cvt.u32.u64 %0, t; }" : "=r"(a) : "l"(p));
    return a;
}

// ---------------- mma.sync -------------------------------------------------
__device__ __forceinline__ void mma_tf32(float* c, const uint32_t* a, const uint32_t* b) {
    asm volatile(
        "mma.sync.aligned.m16n8k8.row.col.f32.tf32.tf32.f32 "
        "{%0,%1,%2,%3},{%4,%5,%6,%7},{%8,%9},{%0,%1,%2,%3};\n"
        : "+f"(c[0]), "+f"(c[1]), "+f"(c[2]), "+f"(c[3])
        : "r"(a[0]), "r"(a[1]), "r"(a[2]), "r"(a[3]), "r"(b[0]), "r"(b[1]));
}
__device__ __forceinline__ void mma_bf16(float* c, const uint32_t* a, const uint32_t* b) {
    asm volatile(
        "mma.sync.aligned.m16n8k16.row.col.f32.bf16.bf16.f32 "
        "{%0,%1,%2,%3},{%4,%5,%6,%7},{%8,%9},{%0,%1,%2,%3};\n"
        : "+f"(c[0]), "+f"(c[1]), "+f"(c[2]), "+f"(c[3])
        : "r"(a[0]), "r"(a[1]), "r"(a[2]), "r"(a[3]), "r"(b[0]), "r"(b[1]));
}
#define LDSM_X4(r0, r1, r2, r3, addr) \
    asm volatile("ldmatrix.sync.aligned.m8n8.x4.shared.b16 {%0,%1,%2,%3}, [%4];" \
                 : "=r"(r0), "=r"(r1), "=r"(r2), "=r"(r3) : "r"(addr))

// ---------------- cp.async -------------------------------------------------
__device__ __forceinline__ void cp_async16(uint32_t dst, const void* src) {
    asm volatile("cp.async.cg.shared.global [%0], [%1], 16;" :: "r"(dst), "l"(src));
}
#define CP_COMMIT() asm volatile("cp.async.commit_group;" ::: "memory")
#define CP_WAIT1()  asm volatile("cp.async.wait_group 1;" ::: "memory")

// ---------------- batched weight transpose + split (one launch) -------------
// z selects: 0..2 -> Wq/Wk/Wv into concatenated wqkv; 3 -> Wo; 4 -> W1; 5 -> W2.
__global__ void wsplit_all(const float* __restrict__ Wq, const float* __restrict__ Wk,
                           const float* __restrict__ Wv, const float* __restrict__ Wo,
                           const float* __restrict__ W1, const float* __restrict__ W2,
                           __nv_bfloat16* wqkvh, __nv_bfloat16* wqkvl,
                           __nv_bfloat16* woh,  __nv_bfloat16* wol,
                           __nv_bfloat16* w1h,  __nv_bfloat16* w1l,
                           __nv_bfloat16* w2h,  __nv_bfloat16* w2l) {
    int z = blockIdx.z;
    const float* W;
    __nv_bfloat16 *Th, *Tl;
    int K, N;
    switch (z) {
        case 0: W = Wq; Th = wqkvh;                           Tl = wqkvl;                           K = DIMD; N = DIMD; break;
        case 1: W = Wk; Th = wqkvh + (size_t)DIMD * DIMD;     Tl = wqkvl + (size_t)DIMD * DIMD;     K = DIMD; N = DIMD; break;
        case 2: W = Wv; Th = wqkvh + (size_t)2 * DIMD * DIMD; Tl = wqkvl + (size_t)2 * DIMD * DIMD; K = DIMD; N = DIMD; break;
        case 3: W = Wo; Th = woh; Tl = wol; K = DIMD; N = DIMD; break;
        case 4: W = W1; Th = w1h; Tl = w1l; K = DIMD; N = MLPD; break;
        default: W = W2; Th = w2h; Tl = w2l; K = MLPD; N = DIMD; break;
    }
    if ((int)blockIdx.x >= N / 32 || (int)blockIdx.y >= K / 32) return;

    __shared__ float tile[32][33];
    int kb = blockIdx.y * 32, nb = blockIdx.x * 32;
    int tx = threadIdx.x, ty = threadIdx.y;   // 32 x 8
    #pragma unroll
    for (int i = 0; i < 32; i += 8)
        tile[ty + i][tx] = W[(size_t)(kb + ty + i) * N + nb + tx];
    __syncthreads();
    #pragma unroll
    for (int i = 0; i < 32; i += 8) {
        float v = tile[tx][ty + i];
        __nv_bfloat16 hi, lo;
        split_bf16(v, hi, lo);
        size_t o = (size_t)(nb + ty + i) * K + kb + tx;
        Th[o] = hi;
        Tl[o] = lo;
    }
}

// ---------------- LayerNorm (bf16 hi/lo out) --------------------------------
__global__ void ln_bf16_kernel(const float* __restrict__ x, const float* __restrict__ g,
                               const float* __restrict__ be,
                               __nv_bfloat16* __restrict__ oh,
                               __nv_bfloat16* __restrict__ ol) {
    int row = blockIdx.x;
    int t = threadIdx.x;
    const float4* xr = (const float4*)(x + (size_t)row * DIMD);
    float4 v = xr[t];
    float s  = v.x + v.y + v.z + v.w;
    float sq = v.x * v.x + v.y * v.y + v.z * v.z + v.w * v.w;
    #pragma unroll
    for (int o = 16; o > 0; o >>= 1) {
        s  += __shfl_xor_sync(0xffffffffu, s,  o);
        sq += __shfl_xor_sync(0xffffffffu, sq, o);
    }
    __shared__ float rs_[4], rq_[4];
    int lane = t & 31, w = t >> 5;
    if (lane == 0) { rs_[w] = s; rq_[w] = sq; }
    __syncthreads();
    s  = rs_[0] + rs_[1] + rs_[2] + rs_[3];
    sq = rq_[0] + rq_[1] + rq_[2] + rq_[3];
    float mu  = s * (1.0f / DIMD);
    float var = sq * (1.0f / DIMD) - mu * mu;
    float rstd = rsqrtf(var + 1e-5f);
    float4 gg = ((const float4*)g)[t];
    float4 bb = ((const float4*)be)[t];
    float4 o4;
    o4.x = (v.x - mu) * rstd * gg.x + bb.x;
    o4.y = (v.y - mu) * rstd * gg.y + bb.y;
    o4.z = (v.z - mu) * rstd * gg.z + bb.z;
    o4.w = (v.w - mu) * rstd * gg.w + bb.w;
    __nv_bfloat16 h0, l0, h1, l1, h2, l2, h3, l3;
    split_bf16(o4.x, h0, l0); split_bf16(o4.y, h1, l1);
    split_bf16(o4.z, h2, l2); split_bf16(o4.w, h3, l3);
    uint2 uh, ul;
    uh.x = pack2_bf16(__bfloat162float(h0), __bfloat162float(h1));
    uh.y = pack2_bf16(__bfloat162float(h2), __bfloat162float(h3));
    ul.x = pack2_bf16(__bfloat162float(l0), __bfloat162float(l1));
    ul.y = pack2_bf16(__bfloat162float(l2), __bfloat162float(l3));
    ((uint2*)(oh + (size_t)row * DIMD))[t] = uh;
    ((uint2*)(ol + (size_t)row * DIMD))[t] = ul;
}

// ---------------- pre-split bf16 GEMM, BK=16, 3-stage, ldmatrix -------------
// A_hi/A_lo bf16 [M][K]; B_hi/B_lo bf16 [N][K]. C = A @ B^T.
// TERMS: 3 = hh+hl+lh (fp32-accurate), 2 = hh+hl (drops A_lo term).
#define BF_AH(st)  ((st) * 6144)
#define BF_AL(st)  (18432 + (st) * 6144)
#define BF_BH(st)  (36864 + (st) * 6144)
#define BF_BL(st)  (55296 + (st) * 6144)
#define BF_SMEM    73728

template <int EPI, int OUTBF, int TERMS>
__global__ __launch_bounds__(256, 2) void gemm_bf16p(
    const __nv_bfloat16* __restrict__ Agh, const __nv_bfloat16* __restrict__ Agl,
    const __nv_bfloat16* __restrict__ Bgh, const __nv_bfloat16* __restrict__ Bgl,
    const float* __restrict__ bias, const float* __restrict__ R,
    float* __restrict__ C, __nv_bfloat16* __restrict__ Ch, __nv_bfloat16* __restrict__ Cl,
    int M, int Ncols, int K)
{
    extern __shared__ char dsm[];
    uint32_t sb = smem_u32(dsm);

    int tid = threadIdx.x, wid = tid >> 5, lane = tid & 31;
    int gid = lane >> 2, tg = lane & 3;
    int warpM = wid & 1, warpN = wid >> 1;
    int rowTile = blockIdx.y * 128, colTile = blockIdx.x * 128;

    int lr = tid >> 1;
    uint32_t dOff = (uint32_t)lr * 48 + (tid & 1) * 16;
    int lk = (tid & 1) * 8;

    const __nv_bfloat16* ApH = Agh + (size_t)(rowTile + lr) * K + lk;
    const __nv_bfloat16* ApL = Agl + (size_t)(rowTile + lr) * K + lk;
    const __nv_bfloat16* BpH = Bgh + (size_t)(colTile + lr) * K + lk;
    const __nv_bfloat16* BpL = Bgl + (size_t)(colTile + lr) * K + lk;

    uint32_t aoffL = (uint32_t)(((lane & 7) + 8 * ((lane >> 3) & 1)) * 48
                               + (lane >> 4) * 16);
    uint32_t boffL = (uint32_t)((((lane >> 4) & 1) * 8 + (lane & 7)) * 48
                               + ((lane >> 3) & 1) * 16);

    float acc[4][4][4] = {};
    int nIter = K >> 4;

    #pragma unroll
    for (int s = 0; s < 2; s++) {
        int k0 = s * 16;
        cp_async16(sb + BF_AH(s) + dOff, ApH + k0);
        if (TERMS == 3) cp_async16(sb + BF_AL(s) + dOff, ApL + k0);
        cp_async16(sb + BF_BH(s) + dOff, BpH + k0);
        cp_async16(sb + BF_BL(s) + dOff, BpL + k0);
        CP_COMMIT();
    }

    for (int it = 0; it < nIter; it++) {
        CP_WAIT1();
        __syncthreads();
        int nx = it + 2;
        if (nx < nIter) {
            int st = nx - (nx / 3) * 3;
            int k0 = nx * 16;
            cp_async16(sb + BF_AH(st) + dOff, ApH + k0);
            if (TERMS == 3) cp_async16(sb + BF_AL(st) + dOff, ApL + k0);
            cp_async16(sb + BF_BH(st) + dOff, BpH + k0);
            cp_async16(sb + BF_BL(st) + dOff, BpL + k0);
        }
        CP_COMMIT();

        int cur = it - (it / 3) * 3;
        uint32_t sAh = sb + BF_AH(cur), sAl = sb + BF_AL(cur);
        uint32_t sBh = sb + BF_BH(cur), sBl = sb + BF_BL(cur);

        uint32_t ah[4][4], al[4][4], bh[4][2], bl[4][2];
        #pragma unroll
        for (int mt = 0; mt < 4; mt++) {
            uint32_t ab = (uint32_t)(warpM * 64 + mt * 16) * 48 + aoffL;
            LDSM_X4(ah[mt][0], ah[mt][1], ah[mt][2], ah[mt][3], sAh + ab);
            if (TERMS == 3)
                LDSM_X4(al[mt][0], al[mt][1], al[mt][2], al[mt][3], sAl + ab);
        }
        #pragma unroll
        for (int np = 0; np < 2; np++) {
            uint32_t bb = (uint32_t)(warpN * 32 + np * 16) * 48 + boffL;
            LDSM_X4(bh[2*np][0], bh[2*np][1], bh[2*np+1][0], bh[2*np+1][1], sBh + bb);
            LDSM_X4(bl[2*np][0], bl[2*np][1], bl[2*np+1][0], bl[2*np+1][1], sBl + bb);
        }
        #pragma unroll
        for (int mt = 0; mt < 4; mt++)
            #pragma unroll
            for (int nt = 0; nt < 4; nt++) {
                mma_bf16(acc[mt][nt], ah[mt], bh[nt]);
                mma_bf16(acc[mt][nt], ah[mt], bl[nt]);
                if (TERMS == 3) mma_bf16(acc[mt][nt], al[mt], bh[nt]);
            }
    }

    #pragma unroll
    for (int mt = 0; mt < 4; mt++) {
        #pragma unroll
        for (int nt = 0; nt < 4; nt++) {
            int col  = colTile + warpN * 32 + nt * 8 + tg * 2;
            int row0 = rowTile + warpM * 64 + mt * 16 + gid;
            int row1 = row0 + 8;
            float2 o0 = make_float2(acc[mt][nt][0], acc[mt][nt][1]);
            float2 o1 = make_float2(acc[mt][nt][2], acc[mt][nt][3]);
            if (EPI >= 1) {
                float b0 = bias[col], b1 = bias[col + 1];
                o0.x += b0; o0.y += b1; o1.x += b0; o1.y += b1;
            }
            if (EPI == 2) {
                o0.x = gelu_exact(o0.x); o0.y = gelu_exact(o0.y);
                o1.x = gelu_exact(o1.x); o1.y = gelu_exact(o1.y);
            }
            if (EPI == 3) {
                const float* r0p = R + (size_t)row0 * Ncols + col;
                const float* r1p = R + (size_t)row1 * Ncols + col;
                o0.x += r0p[0]; o0.y += r0p[1];
                o1.x += r1p[0]; o1.y += r1p[1];
            }
            if constexpr (OUTBF) {
                __nv_bfloat16 h0, l0, h1, l1;
                split_bf16(o0.x, h0, l0); split_bf16(o0.y, h1, l1);
                __nv_bfloat162 ph; ph.x = h0; ph.y = h1;
                __nv_bfloat162 pl; pl.x = l0; pl.y = l1;
                *(__nv_bfloat162*)(Ch + (size_t)row0 * Ncols + col) = ph;
                *(__nv_bfloat162*)(Cl + (size_t)row0 * Ncols + col) = pl;
                split_bf16(o1.x, h0, l0); split_bf16(o1.y, h1, l1);
                ph.x = h0; ph.y = h1; pl.x = l0; pl.y = l1;
                *(__nv_bfloat162*)(Ch + (size_t)row1 * Ncols + col) = ph;
                *(__nv_bfloat162*)(Cl + (size_t)row1 * Ncols + col) = pl;
            } else {
                *(float2*)(C + (size_t)row0 * Ncols + col) = o0;
                *(float2*)(C + (size_t)row1 * Ncols + col) = o1;
            }
        }
    }
}

// ---------------- Flash attention -------------------------------------------
// QK: tf32. PV: bf16 with P from softmax registers; V pre-packed to bf16
// pair-rows at tile load (Vb[32][72] u32, stride 72 = conflict-free: banks
// 8*tg + gid all distinct). Q/K/V are slices of fused qkv (row stride QKVD).
#define FLDS 68
#define VB_STRIDE 72
#define FSM_BYTES ((64 * FLDS + 32 * VB_STRIDE + 64 * FLDS) * 4)

__global__ __launch_bounds__(128, 3) void flash_tf32(
    const float* __restrict__ qkv,
    __nv_bfloat16* __restrict__ atth, __nv_bfloat16* __restrict__ attl)
{
    extern __shared__ float sm_[];
    float*    Ks = sm_;
    uint32_t* Vb = (uint32_t*)(sm_ + 64 * FLDS);
    float*    Ps = sm_ + 64 * FLDS + 32 * VB_STRIDE;   // Q staging only

    int z = blockIdx.y, b = z >> 3, hh = z & 7;
    const float* Q = qkv + (size_t)b * SEQ * QKVD + hh * HD;
    const float* K = Q + DIMD;
    const float* V = Q + 2 * DIMD;
    __nv_bfloat16* Oh = atth + (size_t)b * SEQ * DIMD + hh * HD;
    __nv_bfloat16* Ol = attl + (size_t)b * SEQ * DIMD + hh * HD;
    int q0 = blockIdx.x * 64;

    int tid = threadIdx.x, wid = tid >> 5, lane = tid & 31;
    int gid = lane >> 2, tg = lane & 3;
    int rb = wid * 16;

    for (int idx = tid; idx < 64 * 16; idx += 128) {
        int r = idx >> 4, c4 = (idx & 15) * 4;
        float4 a = *(const float4*)(Q + (size_t)(q0 + r) * QKVD + c4);
        a.x *= 0.125f; a.y *= 0.125f; a.z *= 0.125f; a.w *= 0.125f;
        *(float4*)&Ps[r * FLDS + c4] = a;
    }
    __syncthreads();
    uint32_t qf[8][4];
    #pragma unroll
    for (int ki = 0; ki < 8; ki++) {
        int ks = ki * 8;
        qf[ki][0] = __float_as_uint(Ps[(rb + gid    ) * FLDS + ks + tg    ]);
        qf[ki][1] = __float_as_uint(Ps[(rb + gid + 8) * FLDS + ks + tg    ]);
        qf[ki][2] = __float_as_uint(Ps[(rb + gid    ) * FLDS + ks + tg + 4]);
        qf[ki][3] = __float_as_uint(Ps[(rb + gid + 8) * FLDS + ks + tg + 4]);
    }
    __syncthreads();

    float m0 = -1e30f, m1 = -1e30f, l0 = 0.0f, l1 = 0.0f;
    float o[8][4] = {};

    for (int t0 = 0; t0 < SEQ; t0 += 64) {
        // K tile: fp32, row-major (stride FLDS)
        for (int idx = tid; idx < 64 * 16; idx += 128) {
            int r = idx >> 4, c4 = (idx & 15) * 4;
            *(float4*)&Ks[r * FLDS + c4] =
                *(const float4*)(K + (size_t)(t0 + r) * QKVD + c4);
        }
        // V tile: pre-packed bf16 pair-rows Vb[i][n] = (V[2i][n], V[2i+1][n])
        for (int idx = tid; idx < 32 * 16; idx += 128) {
            int i = idx >> 4, c4 = (idx & 15) * 4;
            float4 a = *(const float4*)(V + (size_t)(t0 + 2 * i)     * QKVD + c4);
            float4 bv = *(const float4*)(V + (size_t)(t0 + 2 * i + 1) * QKVD + c4);
            uint4 p;
            p.x = pack2_bf16(a.x, bv.x); p.y = pack2_bf16(a.y, bv.y);
            p.z = pack2_bf16(a.z, bv.z); p.w = pack2_bf16(a.w, bv.w);
            *(uint4*)&Vb[i * VB_STRIDE + c4] = p;
        }
        __syncthreads();

        float s[8][4] = {};
        #pragma unroll
        for (int ki = 0; ki < 8; ki++) {
            int ks = ki * 8;
            #pragma unroll
            for (int nt = 0; nt < 8; nt++) {
                uint32_t bf[2];
                bf[0] = __float_as_uint(Ks[(nt * 8 + gid) * FLDS + ks + tg    ]);
                bf[1] = __float_as_uint(Ks[(nt * 8 + gid) * FLDS + ks + tg + 4]);
                mma_tf32(s[nt], qf[ki], bf);
            }
        }

        float tm0 = -1e30f, tm1 = -1e30f;
        #pragma unroll
        for (int nt = 0; nt < 8; nt++) {
            tm0 = fmaxf(tm0, fmaxf(s[nt][0], s[nt][1]));
            tm1 = fmaxf(tm1, fmaxf(s[nt][2], s[nt][3]));
        }
        tm0 = fmaxf(tm0, __shfl_xor_sync(0xffffffffu, tm0, 1));
        tm0 = fmaxf(tm0, __shfl_xor_sync(0xffffffffu, tm0, 2));
        tm1 = fmaxf(tm1, __shfl_xor_sync(0xffffffffu, tm1, 1));
        tm1 = fmaxf(tm1, __shfl_xor_sync(0xffffffffu, tm1, 2));
        float nm0 = fmaxf(m0, tm0), nm1 = fmaxf(m1, tm1);
        float r0 = __expf(m0 - nm0), r1 = __expf(m1 - nm1);
        float sum0 = 0.0f, sum1 = 0.0f;
        #pragma unroll
        for (int nt = 0; nt < 8; nt++) {
            s[nt][0] = __expf(s[nt][0] - nm0);
            s[nt][1] = __expf(s[nt][1] - nm0);
            s[nt][2] = __expf(s[nt][2] - nm1);
            s[nt][3] = __expf(s[nt][3] - nm1);
            sum0 += s[nt][0] + s[nt][1];
            sum1 += s[nt][2] + s[nt][3];
        }
        sum0 += __shfl_xor_sync(0xffffffffu, sum0, 1);
        sum0 += __shfl_xor_sync(0xffffffffu, sum0, 2);
        sum1 += __shfl_xor_sync(0xffffffffu, sum1, 1);
        sum1 += __shfl_xor_sync(0xffffffffu, sum1, 2);
        l0 = l0 * r0 + sum0;
        l1 = l1 * r1 + sum1;
        m0 = nm0; m1 = nm1;
        #pragma unroll
        for (int nt = 0; nt < 8; nt++) {
            o[nt][0] *= r0; o[nt][1] *= r0;
            o[nt][2] *= r1; o[nt][3] *= r1;
        }

        // ---- O += P @ V : P bf16 A-frags from registers; V from Vb ----
        #pragma unroll
        for (int g = 0; g < 4; g++) {          // k16 windows over 64 keys
            uint32_t af[4];
            af[0] = pack2_bf16(s[2*g    ][0], s[2*g    ][1]);
            af[1] = pack2_bf16(s[2*g    ][2], s[2*g    ][3]);
            af[2] = pack2_bf16(s[2*g + 1][0], s[2*g + 1][1]);
            af[3] = pack2_bf16(s[2*g + 1][2], s[2*g + 1][3]);
            int pr = g * 8 + tg;               // pair-row
            #pragma unroll
            for (int nt = 0; nt < 8; nt++) {
                int n = nt * 8 + gid;
                uint32_t bf[2];
                bf[0] = Vb[(pr    ) * VB_STRIDE + n];
                bf[1] = Vb[(pr + 4) * VB_STRIDE + n];
                mma_bf16(o[nt], af, bf);
            }
        }
        __syncthreads();
    }

    float inv0 = 1.0f / l0, inv1 = 1.0f / l1;
    int row0 = q0 + rb + gid, row1 = row0 + 8;
    #pragma unroll
    for (int nt = 0; nt < 8; nt++) {
        int col = nt * 8 + tg * 2;
        float v00 = o[nt][0] * inv0, v01 = o[nt][1] * inv0;
        float v10 = o[nt][2] * inv1, v11 = o[nt][3] * inv1;
        __nv_bfloat16 h0, lo0, h1, lo1;
        split_bf16(v00, h0, lo0); split_bf16(v01, h1, lo1);
        __nv_bfloat162 ph; ph.x = h0; ph.y = h1;
        __nv_bfloat162 pl; pl.x = lo0; pl.y = lo1;
        *(__nv_bfloat162*)(Oh + (size_t)row0 * DIMD + col) = ph;
        *(__nv_bfloat162*)(Ol + (size_t)row0 * DIMD + col) = pl;
        split_bf16(v10, h0, lo0); split_bf16(v11, h1, lo1);
        ph.x = h0; ph.y = h1; pl.x = lo0; pl.y = lo1;
        *(__nv_bfloat162*)(Oh + (size_t)row1 * DIMD + col) = ph;
        *(__nv_bfloat162*)(Ol + (size_t)row1 * DIMD + col) = pl;
    }
}

// ---------------- launch ----------------------------------------------------
extern "C" void kernel_launch(void* const* d_in, const int* in_sizes, int n_in,
                              void* d_out, int out_size) {
    const float* x   = (const float*)d_in[0];
    const float* Wq  = (const float*)d_in[1];
    const float* Wk  = (const float*)d_in[2];
    const float* Wv  = (const float*)d_in[3];
    const float* Wo  = (const float*)d_in[4];
    const float* bo  = (const float*)d_in[5];
    const float* W1  = (const float*)d_in[6];
    const float* b1  = (const float*)d_in[7];
    const float* W2  = (const float*)d_in[8];
    const float* b2  = (const float*)d_in[9];
    const float* g1  = (const float*)d_in[10];
    const float* be1 = (const float*)d_in[11];
    const float* g2  = (const float*)d_in[12];
    const float* be2 = (const float*)d_in[13];
    float* out = (float*)d_out;

    float *qkv, *xm;
    __nv_bfloat16 *h2h, *h2l, *atth, *attl, *ffh, *ffl;
    __nv_bfloat16 *wqkvh, *wqkvl, *woh, *wol, *w1h, *w1l, *w2h, *w2l;
    cudaGetSymbolAddress((void**)&qkv,  g_qkv);
    cudaGetSymbolAddress((void**)&xm,   g_xm);
    cudaGetSymbolAddress((void**)&h2h,  g_h2h);
    cudaGetSymbolAddress((void**)&h2l,  g_h2l);
    cudaGetSymbolAddress((void**)&atth, g_atth);
    cudaGetSymbolAddress((void**)&attl, g_attl);
    cudaGetSymbolAddress((void**)&ffh,  g_ffh);
    cudaGetSymbolAddress((void**)&ffl,  g_ffl);
    cudaGetSymbolAddress((void**)&wqkvh, g_wqkvh); cudaGetSymbolAddress((void**)&wqkvl, g_wqkvl);
    cudaGetSymbolAddress((void**)&woh, g_woh); cudaGetSymbolAddress((void**)&wol, g_wol);
    cudaGetSymbolAddress((void**)&w1h, g_w1h); cudaGetSymbolAddress((void**)&w1l, g_w1l);
    cudaGetSymbolAddress((void**)&w2h, g_w2h); cudaGetSymbolAddress((void**)&w2l, g_w2l);

    cudaFuncSetAttribute(flash_tf32,
                         cudaFuncAttributeMaxDynamicSharedMemorySize, FSM_BYTES);
    cudaFuncSetAttribute(gemm_bf16p<0, 0, 2>,
                         cudaFuncAttributeMaxDynamicSharedMemorySize, BF_SMEM);
    cudaFuncSetAttribute(gemm_bf16p<3, 0, 2>,
                         cudaFuncAttributeMaxDynamicSharedMemorySize, BF_SMEM);
    cudaFuncSetAttribute(gemm_bf16p<2, 1, 3>,
                         cudaFuncAttributeMaxDynamicSharedMemorySize, BF_SMEM);
    cudaFuncSetAttribute(gemm_bf16p<3, 0, 3>,
                         cudaFuncAttributeMaxDynamicSharedMemorySize, BF_SMEM);

    dim3 gQKV(QKVD / 128, BN_TOK / 128);        // (12, 64)
    dim3 gProj(DIMD / 128, BN_TOK / 128);       // (4, 64)
    dim3 gMlp(MLPD / 128, BN_TOK / 128);        // (16, 64)

    // 0) all weight transposes + bf16 splits in ONE launch
    wsplit_all<<<dim3(MLPD / 32, MLPD / 32, 6), dim3(32, 8)>>>(
        Wq, Wk, Wv, Wo, W1, W2,
        wqkvh, wqkvl, woh, wol, w1h, w1l, w2h, w2l);
    // 1) h = LN(x; g1, be1) -> split
    ln_bf16_kernel<<<BN_TOK, 128>>>(x, g1, be1, h2h, h2l);
    // 2) fused q|k|v projection (bf16 2-term)
    gemm_bf16p<0, 0, 2><<<gQKV, 256, BF_SMEM>>>(h2h, h2l, wqkvh, wqkvl, nullptr, nullptr,
                                                qkv, nullptr, nullptr, BN_TOK, QKVD, DIMD);
    // 3-5) fused flash attention -> split att
    flash_tf32<<<dim3(SEQ / 64, BATCH * HEADS), 128, FSM_BYTES>>>(qkv, atth, attl);
    // 6) xm = x + att @ Wo + bo  (bf16 2-term)
    gemm_bf16p<3, 0, 2><<<gProj, 256, BF_SMEM>>>(atth, attl, woh, wol, bo, x,
                                                 xm, nullptr, nullptr, BN_TOK, DIMD, DIMD);
    // 7) h2 = LN(xm; g2, be2) -> split
    ln_bf16_kernel<<<BN_TOK, 128>>>(xm, g2, be2, h2h, h2l);
    // 8) ff = gelu(h2 @ W1 + b1) -> split  (bf16x3)
    gemm_bf16p<2, 1, 3><<<gMlp, 256, BF_SMEM>>>(h2h, h2l, w1h, w1l, b1, nullptr,
                                                nullptr, ffh, ffl, BN_TOK, MLPD, DIMD);
    // 9) out = xm + ff @ W2 + b2  (bf16x3)
    gemm_bf16p<3, 0, 3><<<gProj, 256, BF_SMEM>>>(ffh, ffl, w2h, w2l, b2, xm,
                                                 out, nullptr, nullptr, BN_TOK, DIMD, MLPD);
}